// round 10
// baseline (speedup 1.0000x reference)
#include <cuda_runtime.h>
#include <cuda_fp16.h>
#include <stdint.h>

#define TPB        1024
#define CNT        8192
#define SPG        8192
#define CHUNK_PTS  256
#define NCHUNK     (CNT / CHUNK_PTS)            // 32 chunks per group
#define ARR_BYTES  (CHUNK_PTS * 9 * 4)          // 9216 B per array per chunk
#define RAW_SLOT_B (2 * ARR_BYTES)              // 18432 B per slot
#define NSLOT      7
#define IL         (NSLOT - 1)                  // issue lookahead
#define NDEMUX     (2 * CHUNK_PTS)              // 512 demux threads (16 warps)
#define BUF_B      (12 * CNT)                   // 98304 B fp16 point buffer
#define MBAR_OFF   (BUF_B + NSLOT * RAW_SLOT_B) // 227328
#define SMEM_BYTES (MBAR_OFF + 16 * NSLOT)      // 227440 B

__device__ double g_acc = 0.0;
__device__ unsigned int g_count = 0;

__device__ __forceinline__ uint32_t smem_u32(const void* p) {
    return (uint32_t)__cvta_generic_to_shared(p);
}
__device__ __forceinline__ void mbar_init(uint32_t mbar, uint32_t cnt) {
    asm volatile("mbarrier.init.shared.b64 [%0], %1;" :: "r"(mbar), "r"(cnt) : "memory");
}
__device__ __forceinline__ void mbar_arrive(uint32_t mbar) {
    asm volatile("mbarrier.arrive.shared.b64 _, [%0];" :: "r"(mbar) : "memory");
}
__device__ __forceinline__ void mbar_expect_tx(uint32_t mbar, uint32_t bytes) {
    asm volatile("mbarrier.arrive.expect_tx.shared.b64 _, [%0], %1;"
                 :: "r"(mbar), "r"(bytes) : "memory");
}
__device__ __forceinline__ void mbar_wait(uint32_t mbar, uint32_t parity) {
    uint32_t done;
    asm volatile(
        "{\n\t.reg .pred p;\n\t"
        "mbarrier.try_wait.parity.acquire.cta.shared::cta.b64 p, [%1], %2;\n\t"
        "selp.b32 %0, 1, 0, p;\n\t}"
        : "=r"(done) : "r"(mbar), "r"(parity) : "memory");
    if (!done) {
        asm volatile(
            "{\n\t.reg .pred P1;\n\t"
            "W_%=:\n\t"
            "mbarrier.try_wait.parity.acquire.cta.shared::cta.b64 P1, [%0], %1, 0x989680;\n\t"
            "@P1 bra.uni D_%=;\n\t"
            "bra.uni W_%=;\n\t"
            "D_%=:\n\t}"
            :: "r"(mbar), "r"(parity) : "memory");
    }
}
__device__ __forceinline__ void bulk_copy(uint32_t dst, const void* src,
                                          uint32_t bytes, uint32_t mbar) {
    asm volatile(
        "cp.async.bulk.shared::cta.global.mbarrier::complete_tx::bytes [%0], [%1], %2, [%3];"
        :: "r"(dst), "l"(src), "r"(bytes), "r"(mbar) : "memory");
}

__device__ __forceinline__ float pair_term(int l, int r, const __half2* __restrict__ buf)
{
    float2 a  = __half22float2(buf[3 * l + 0]);   // in.xy
    float2 mz = __half22float2(buf[3 * l + 1]);   // (in.z, tg.z)
    float2 c  = __half22float2(buf[3 * l + 2]);   // tg.xy
    float2 b  = __half22float2(buf[3 * r + 0]);
    float2 nz = __half22float2(buf[3 * r + 1]);
    float2 d  = __half22float2(buf[3 * r + 2]);

    float ux = a.x - b.x, uy = a.y - b.y, uz = mz.x - nz.x;
    float d_in = sqrtf(fmaf(ux, ux, fmaf(uy, uy, uz * uz)));

    float vx = c.x - d.x, vy = c.y - d.y, vz = mz.y - nz.y;
    float d_tg = sqrtf(fmaf(vx, vx, fmaf(vy, vy, vz * vz)));

    float t = d_in - d_tg;
    return t * t;
}

__global__ void __launch_bounds__(TPB, 1)
rgn_pipe_kernel(const float* __restrict__ inputs,
                const float* __restrict__ target,
                const int* __restrict__ left,
                const int* __restrict__ right,
                float* __restrict__ out,
                int npairs, int ngroups)
{
    extern __shared__ unsigned char smem[];
    unsigned char* bufb = smem;                  // fp16 buffer, 12 B/point
    __half2* buf = (__half2*)smem;
    float* raw = (float*)(smem + BUF_B);         // NSLOT raw chunk slots
    const uint32_t raw_u32 = smem_u32(raw);
    const uint32_t mb = smem_u32(smem + MBAR_OFF);
    // full[s] = mb + 16s ; empty[s] = mb + 16s + 8

    const int K = (ngroups - blockIdx.x + gridDim.x - 1) / gridDim.x;
    const int total = K * NCHUNK;

    if (threadIdx.x == 0) {
        #pragma unroll
        for (int s = 0; s < NSLOT; s++) {
            mbar_init(mb + 16 * s, 1);                 // full: 1 expect_tx arrive
            mbar_init(mb + 16 * s + 8, NDEMUX / 32);   // empty: 16 warp arrivals
        }
    }
    __syncthreads();

    auto issue = [&](int ic) {
        const int g  = blockIdx.x + (ic / NCHUNK) * gridDim.x;
        const int ci = ic & (NCHUNK - 1);
        const int s  = ic % NSLOT;
        const uint32_t slot = raw_u32 + (uint32_t)s * RAW_SLOT_B;
        const uint32_t fullb = mb + 16 * s;
        const float* sin = inputs + (size_t)g * CNT * 9 + (size_t)ci * CHUNK_PTS * 9;
        const float* stg = target + (size_t)g * CNT * 9 + (size_t)ci * CHUNK_PTS * 9;
        mbar_expect_tx(fullb, RAW_SLOT_B);
        bulk_copy(slot, sin, ARR_BYTES, fullb);
        bulk_copy(slot + ARR_BYTES, stg, ARR_BYTES, fullb);
    };

    if (threadIdx.x == 0) {
        #pragma unroll
        for (int k = 0; k < IL; k++)
            if (k < total) issue(k);   // fresh slots, no empty-wait needed
    }

    float acc = 0.0f;
    for (int cc = 0; cc < total; cc++) {
        // producer: keep the ring full (lookahead IL)
        if (threadIdx.x == 0 && cc + IL < total) {
            const int ic = cc + IL;
            const int k  = ic / NSLOT;
            if (k > 0) mbar_wait(mb + 16 * (ic % NSLOT) + 8, (uint32_t)(((k - 1) & 1)));
            issue(ic);
        }

        // demux warps: wait chunk, compact into fp16 buffer, release slot
        if (threadIdx.x < NDEMUX) {
            const int s = cc % NSLOT;
            mbar_wait(mb + 16 * s, (uint32_t)((cc / NSLOT) & 1));

            const float* slot = raw + (size_t)s * (RAW_SLOT_B / 4);
            const int ci = cc & (NCHUNK - 1);
            const int t = threadIdx.x;
            if (t < CHUNK_PTS) {
                const float* r = slot + 9 * t + 3;                  // inputs CA row
                const int p = ci * CHUNK_PTS + t;
                *(__half2*)(bufb + 12 * p)     = __floats2half2_rn(r[0], r[1]);
                *(__half*) (bufb + 12 * p + 4) = __float2half_rn(r[2]);
            } else {
                const int q = t - CHUNK_PTS;
                const float* r = slot + CHUNK_PTS * 9 + 9 * q + 3;  // target CA row
                const int p = ci * CHUNK_PTS + q;
                *(__half*) (bufb + 12 * p + 6) = __float2half_rn(r[2]);
                *(__half2*)(bufb + 12 * p + 8) = __floats2half2_rn(r[0], r[1]);
            }
            if ((threadIdx.x & 31) == 0) mbar_arrive(mb + 16 * s + 8);
        }

        if ((cc & (NCHUNK - 1)) == (NCHUNK - 1)) {
            __syncthreads();   // whole group demuxed & visible
            const int g = blockIdx.x + (cc / NCHUNK) * gridDim.x;
            const int4* Lg = (const int4*)(left  + (size_t)g * SPG);
            const int4* Rg = (const int4*)(right + (size_t)g * SPG);
            #pragma unroll
            for (int j = 0; j < SPG / (4 * TPB); j++) {   // 2 iters, 4 pairs each
                const int i = threadIdx.x + j * TPB;
                int4 L = __ldg(Lg + i);
                int4 R = __ldg(Rg + i);
                acc += pair_term(L.x & (CNT - 1), R.x & (CNT - 1), buf);
                acc += pair_term(L.y & (CNT - 1), R.y & (CNT - 1), buf);
                acc += pair_term(L.z & (CNT - 1), R.z & (CNT - 1), buf);
                acc += pair_term(L.w & (CNT - 1), R.w & (CNT - 1), buf);
            }
            __syncthreads();   // buf reads done before next group's demux overwrites
        }
    }

    // block reduce
    #pragma unroll
    for (int off = 16; off > 0; off >>= 1)
        acc += __shfl_down_sync(0xFFFFFFFFu, acc, off);

    __shared__ float warp_sums[TPB / 32];
    const int lane = threadIdx.x & 31;
    const int wid  = threadIdx.x >> 5;
    if (lane == 0) warp_sums[wid] = acc;
    __syncthreads();

    if (wid == 0) {
        float s = (lane < TPB / 32) ? warp_sums[lane] : 0.0f;
        #pragma unroll
        for (int off = 16; off > 0; off >>= 1)
            s += __shfl_down_sync(0xFFFFFFFFu, s, off);

        if (lane == 0) {
            atomicAdd(&g_acc, (double)s);
            __threadfence();
            unsigned int done = atomicAdd(&g_count, 1u);
            if (done == gridDim.x - 1) {
                out[0] = (float)(g_acc / (double)npairs);
                g_acc = 0.0;     // reset for next graph replay
                g_count = 0;
            }
        }
    }
}

extern "C" void kernel_launch(void* const* d_in, const int* in_sizes, int n_in,
                              void* d_out, int out_size) {
    const float* inputs = (const float*)d_in[0];
    const float* target = (const float*)d_in[1];
    const int*   left   = (const int*)d_in[2];
    const int*   right  = (const int*)d_in[3];
    float* out = (float*)d_out;

    int npairs  = in_sizes[2];
    int ngroups = npairs / SPG;   // 512

    static int num_sms = 0;
    if (num_sms == 0) {
        cudaDeviceProp prop;
        cudaGetDeviceProperties(&prop, 0);
        num_sms = prop.multiProcessorCount;   // 152 on GB300
    }
    int grid = (num_sms < ngroups) ? num_sms : ngroups;

    cudaFuncSetAttribute(rgn_pipe_kernel,
                         cudaFuncAttributeMaxDynamicSharedMemorySize, SMEM_BYTES);

    rgn_pipe_kernel<<<grid, TPB, SMEM_BYTES>>>(inputs, target, left, right,
                                               out, npairs, ngroups);
}

// round 13
// speedup vs baseline: 1.0633x; 1.0633x over previous
#include <cuda_runtime.h>
#include <cuda_fp16.h>
#include <stdint.h>

#define TPB        1024
#define CNT        8192
#define SPG        8192
#define CHUNK_PTS  256
#define NCHUNK     (CNT / CHUNK_PTS)            // 32 chunks per group
#define ARR_BYTES  (CHUNK_PTS * 9 * 4)          // 9216 B per array per chunk
#define RAW_SLOT_B (2 * ARR_BYTES)              // 18432 B per slot
#define NSLOT      7
#define IL         (NSLOT - 1)                  // issue lookahead = 6 chunks (~110 KB)
#define BUF_B      (12 * CNT)                   // 98304 B fp16 point buffer
#define MBAR_OFF   (BUF_B + NSLOT * RAW_SLOT_B) // 227328
#define SMEM_BYTES (MBAR_OFF + 8 * NSLOT)       // 227384 B

__device__ double g_acc = 0.0;
__device__ unsigned int g_count = 0;

__device__ __forceinline__ uint32_t smem_u32(const void* p) {
    return (uint32_t)__cvta_generic_to_shared(p);
}
__device__ __forceinline__ void mbar_init(uint32_t mbar, uint32_t cnt) {
    asm volatile("mbarrier.init.shared.b64 [%0], %1;" :: "r"(mbar), "r"(cnt) : "memory");
}
__device__ __forceinline__ void mbar_expect_tx(uint32_t mbar, uint32_t bytes) {
    asm volatile("mbarrier.arrive.expect_tx.shared.b64 _, [%0], %1;"
                 :: "r"(mbar), "r"(bytes) : "memory");
}
__device__ __forceinline__ void mbar_wait(uint32_t mbar, uint32_t parity) {
    uint32_t done;
    asm volatile(
        "{\n\t.reg .pred p;\n\t"
        "mbarrier.try_wait.parity.acquire.cta.shared::cta.b64 p, [%1], %2;\n\t"
        "selp.b32 %0, 1, 0, p;\n\t}"
        : "=r"(done) : "r"(mbar), "r"(parity) : "memory");
    if (!done) {
        asm volatile(
            "{\n\t.reg .pred P1;\n\t"
            "W_%=:\n\t"
            "mbarrier.try_wait.parity.acquire.cta.shared::cta.b64 P1, [%0], %1, 0x989680;\n\t"
            "@P1 bra.uni D_%=;\n\t"
            "bra.uni W_%=;\n\t"
            "D_%=:\n\t}"
            :: "r"(mbar), "r"(parity) : "memory");
    }
}
__device__ __forceinline__ void bulk_copy(uint32_t dst, const void* src,
                                          uint32_t bytes, uint32_t mbar) {
    asm volatile(
        "cp.async.bulk.shared::cta.global.mbarrier::complete_tx::bytes [%0], [%1], %2, [%3];"
        :: "r"(dst), "l"(src), "r"(bytes), "r"(mbar) : "memory");
}

__device__ __forceinline__ float pair_term(int l, int r, const __half2* __restrict__ buf)
{
    float2 a  = __half22float2(buf[3 * l + 0]);   // in.xy
    float2 mz = __half22float2(buf[3 * l + 1]);   // (in.z, tg.z)
    float2 c  = __half22float2(buf[3 * l + 2]);   // tg.xy
    float2 b  = __half22float2(buf[3 * r + 0]);
    float2 nz = __half22float2(buf[3 * r + 1]);
    float2 d  = __half22float2(buf[3 * r + 2]);

    float ux = a.x - b.x, uy = a.y - b.y, uz = mz.x - nz.x;
    float d_in = sqrtf(fmaf(ux, ux, fmaf(uy, uy, uz * uz)));

    float vx = c.x - d.x, vy = c.y - d.y, vz = mz.y - nz.y;
    float d_tg = sqrtf(fmaf(vx, vx, fmaf(vy, vy, vz * vz)));

    float t = d_in - d_tg;
    return t * t;
}

__global__ void __launch_bounds__(TPB, 1)
rgn_bulk7_kernel(const float* __restrict__ inputs,
                 const float* __restrict__ target,
                 const int* __restrict__ left,
                 const int* __restrict__ right,
                 float* __restrict__ out,
                 int npairs, int ngroups)
{
    extern __shared__ unsigned char smem[];
    unsigned char* bufb = smem;                  // fp16 buffer, 12 B/point
    __half2* buf = (__half2*)smem;
    float* raw = (float*)(smem + BUF_B);         // NSLOT raw chunk slots
    const uint32_t raw_u32 = smem_u32(raw);
    const uint32_t mb0 = smem_u32(smem + MBAR_OFF);

    const int K = (ngroups - blockIdx.x + gridDim.x - 1) / gridDim.x;
    const int total = K * NCHUNK;

    if (threadIdx.x == 0) {
        #pragma unroll
        for (int s = 0; s < NSLOT; s++) mbar_init(mb0 + 8 * s, 1);
    }
    __syncthreads();

    // issue a chunk: expect_tx + 2 bulk copies, single thread (same as R9)
    auto issue = [&](int cc) {
        const int g  = blockIdx.x + (cc / NCHUNK) * gridDim.x;
        const int ci = cc & (NCHUNK - 1);
        const int s  = cc % NSLOT;
        const uint32_t slot = raw_u32 + (uint32_t)s * RAW_SLOT_B;
        const uint32_t mbar = mb0 + 8 * s;
        const float* sin = inputs + (size_t)g * CNT * 9 + (size_t)ci * CHUNK_PTS * 9;
        const float* stg = target + (size_t)g * CNT * 9 + (size_t)ci * CHUNK_PTS * 9;
        mbar_expect_tx(mbar, RAW_SLOT_B);
        bulk_copy(slot, sin, ARR_BYTES, mbar);
        bulk_copy(slot + ARR_BYTES, stg, ARR_BYTES, mbar);
    };

    if (threadIdx.x == 0) {
        #pragma unroll
        for (int k = 0; k < IL; k++)
            if (k < total) issue(k);          // fresh slots, no reuse hazard
    }

    float acc = 0.0f;
    for (int cc = 0; cc < total; cc++) {
        // reuse-safety: slot (cc+IL)%NSLOT == (cc-1)%NSLOT, demuxed & sync'd at iter cc-1
        if (threadIdx.x == 0 && cc + IL < total) issue(cc + IL);

        mbar_wait(mb0 + 8 * (cc % NSLOT), (uint32_t)((cc / NSLOT) & 1));

        // demux chunk cc: raw slot -> fp16 buffer (stride-9 word LDS: conflict-free)
        {
            const float* slot = raw + (size_t)(cc % NSLOT) * (RAW_SLOT_B / 4);
            const int ci = cc & (NCHUNK - 1);
            const int t = threadIdx.x;
            if (t < CHUNK_PTS) {
                const float* r = slot + 9 * t + 3;                  // inputs CA row
                const int p = ci * CHUNK_PTS + t;
                *(__half2*)(bufb + 12 * p)     = __floats2half2_rn(r[0], r[1]);
                *(__half*) (bufb + 12 * p + 4) = __float2half_rn(r[2]);
            } else if (t < 2 * CHUNK_PTS) {
                const int q = t - CHUNK_PTS;
                const float* r = slot + CHUNK_PTS * 9 + 9 * q + 3;  // target CA row
                const int p = ci * CHUNK_PTS + q;
                *(__half*) (bufb + 12 * p + 6) = __float2half_rn(r[2]);
                *(__half2*)(bufb + 12 * p + 8) = __floats2half2_rn(r[0], r[1]);
            }
        }
        __syncthreads();   // demux done -> slot reusable next iters; buf writes visible

        if ((cc & (NCHUNK - 1)) == (NCHUNK - 1)) {
            // group fully staged; consume (next 6 chunks already in flight)
            const int g = blockIdx.x + (cc / NCHUNK) * gridDim.x;
            const int4* Lg = (const int4*)(left  + (size_t)g * SPG);
            const int4* Rg = (const int4*)(right + (size_t)g * SPG);
            #pragma unroll
            for (int j = 0; j < SPG / (4 * TPB); j++) {   // 2 iters, 4 pairs each
                const int i = threadIdx.x + j * TPB;
                int4 L = __ldg(Lg + i);
                int4 R = __ldg(Rg + i);
                acc += pair_term(L.x & (CNT - 1), R.x & (CNT - 1), buf);
                acc += pair_term(L.y & (CNT - 1), R.y & (CNT - 1), buf);
                acc += pair_term(L.z & (CNT - 1), R.z & (CNT - 1), buf);
                acc += pair_term(L.w & (CNT - 1), R.w & (CNT - 1), buf);
            }
            __syncthreads();   // buf reads done before next group's demux overwrites
        }
    }

    // block reduce
    #pragma unroll
    for (int off = 16; off > 0; off >>= 1)
        acc += __shfl_down_sync(0xFFFFFFFFu, acc, off);

    __shared__ float warp_sums[TPB / 32];
    const int lane = threadIdx.x & 31;
    const int wid  = threadIdx.x >> 5;
    if (lane == 0) warp_sums[wid] = acc;
    __syncthreads();

    if (wid == 0) {
        float s = (lane < TPB / 32) ? warp_sums[lane] : 0.0f;
        #pragma unroll
        for (int off = 16; off > 0; off >>= 1)
            s += __shfl_down_sync(0xFFFFFFFFu, s, off);

        if (lane == 0) {
            atomicAdd(&g_acc, (double)s);
            __threadfence();
            unsigned int done = atomicAdd(&g_count, 1u);
            if (done == gridDim.x - 1) {
                out[0] = (float)(g_acc / (double)npairs);
                g_acc = 0.0;     // reset for next graph replay
                g_count = 0;
            }
        }
    }
}

extern "C" void kernel_launch(void* const* d_in, const int* in_sizes, int n_in,
                              void* d_out, int out_size) {
    const float* inputs = (const float*)d_in[0];
    const float* target = (const float*)d_in[1];
    const int*   left   = (const int*)d_in[2];
    const int*   right  = (const int*)d_in[3];
    float* out = (float*)d_out;

    int npairs  = in_sizes[2];
    int ngroups = npairs / SPG;   // 512

    static int num_sms = 0;
    if (num_sms == 0) {
        cudaDeviceProp prop;
        cudaGetDeviceProperties(&prop, 0);
        num_sms = prop.multiProcessorCount;   // 152 on GB300
    }
    int grid = (num_sms < ngroups) ? num_sms : ngroups;

    cudaFuncSetAttribute(rgn_bulk7_kernel,
                         cudaFuncAttributeMaxDynamicSharedMemorySize, SMEM_BYTES);

    rgn_bulk7_kernel<<<grid, TPB, SMEM_BYTES>>>(inputs, target, left, right,
                                                out, npairs, ngroups);
}